// round 16
// baseline (speedup 1.0000x reference)
#include <cuda_runtime.h>
#include <cuda_bf16.h>

// Problem constants (fixed by the reference setup_inputs)
#define NB    8      // batch
#define HH    28     // input H = W
#define NC    32     // channels (== warp size == one 128B line of floats)
#define HO    14     // output H = W
#define NOUT  196    // HO*HO
#define NIN   784    // HH*HH

#define NTILE (NB * NOUT)       // 1568 (b,i) tiles
#define NUNIT (NTILE * 8)       // 12544 warp work units (tile, chunk)
#define GRIDB 888

// Scratch: flat input spatial index of the per-(b,i,c) argmax,
// laid out [b][i][c] so a warp (lane=c) reads one coalesced line per i.
__device__ int g_sidx[NB * NOUT * NC];
__device__ unsigned g_unitctr;   // dynamic warp-unit counter (reset by A)

// ---------------------------------------------------------------------------
// Kernel A: 2x2 max-pool argmax -> mu_out + gather index; resets unit ctr.
// One thread per (b, oy, ox, c); 50176 threads total (98 blocks x 512).
// ---------------------------------------------------------------------------
__global__ void pool_idx_kernel(const float* __restrict__ mu,
                                float* __restrict__ out_mu) {
    int t = blockIdx.x * blockDim.x + threadIdx.x;
    if (t == 0) g_unitctr = 0;   // reset for this replay (PDL-ordered vs B)
    if (t < NB * NOUT * NC) {
        int c = t & (NC - 1);
        int p = t >> 5;            // b*196 + i
        int i = p % NOUT;
        int oy = i / HO, ox = i - oy * HO;
        int iy = 2 * oy, ix = 2 * ox;
        int b = p / NOUT;

        const float* base = mu + ((b * HH + iy) * HH + ix) * NC + c;
        float v00 = base[0];
        float v01 = base[NC];
        float v10 = base[HH * NC];
        float v11 = base[HH * NC + NC];

        // first-match argmax over row-major order (0,0),(0,1),(1,0),(1,1)
        float best = v00; int k = 0;
        if (v01 > best) { best = v01; k = 1; }
        if (v10 > best) { best = v10; k = 2; }
        if (v11 > best) { best = v11; k = 3; }
        int dy = k >> 1, dx = k & 1;

        out_mu[t] = best;
        g_sidx[t] = (iy + dy) * HH + (ix + dx);   // flat input spatial index
    }
    // PDL: allow the dependent gather kernel to begin its prologue early.
    cudaTriggerProgrammaticLaunchCompletion();
}

// ---------------------------------------------------------------------------
// Kernel B: Sigma double-gather — R12's proven per-chunk body, with WARP-
// level dynamic work claiming: unit = (tile, chunk), chunk in 0..7 (chunks
// 0-3: 25 j's, 4-7: 24). atomicAdd + shfl broadcast per warp — NO block
// barriers, so warps keep R12's cross-tile pipeline overlap while getting
// near-perfect balance over 12544 units (R15 showed block-level claiming
// with __syncthreads costs more than the balance wins).
// Per chunk: lane = channel c; column indices preloaded (L2-resident),
// all gathers issued back-to-back (evict-first; zero reuse), coalesced
// 128B streaming stores.
// ---------------------------------------------------------------------------
#define JBASE 24

__global__ void __launch_bounds__(256)
sigma_gather_kernel(const float* __restrict__ S, float* __restrict__ outS) {
    int c = threadIdx.x & 31;

    // Wait for pool_idx_kernel's g_sidx writes + counter reset (PDL).
    cudaGridDependencySynchronize();

    for (;;) {
        unsigned u = 0;
        if (c == 0) u = atomicAdd(&g_unitctr, 1u);
        u = __shfl_sync(0xffffffffu, u, 0);
        if (u >= NUNIT) break;

        unsigned tile = u >> 3;
        int cw = (int)(u & 7u);          // chunk id 0..7
        bool extra = (cw < 4);
        int jbeg = extra ? (cw * 25) : (100 + (cw - 4) * 24);

        int b = (int)tile / NOUT;

        float* __restrict__ o =
            outS + ((long long)tile * NOUT) * NC + c;
        const int* __restrict__ sj_base = &g_sidx[b * NOUT * NC + c];

        int my_sidx = __ldg(&g_sidx[tile * NC + c]);
        const float* __restrict__ Sp =
            S + (long long)b * (NIN * (long long)NIN * NC)
              + (long long)my_sidx * (NIN * NC) + c;

        // preload column spatial indices (L2-resident scratch)
        int sj[JBASE];
#pragma unroll
        for (int t = 0; t < JBASE; t++)
            sj[t] = __ldg(sj_base + (jbeg + t) * NC);
        int sj24 = 0;
        if (extra) sj24 = __ldg(sj_base + (jbeg + JBASE) * NC);

        // issue all gathers back-to-back (evict-first: zero reuse)
        float v[JBASE];
#pragma unroll
        for (int t = 0; t < JBASE; t++)
            v[t] = __ldcs(Sp + (long long)sj[t] * NC);
        float v24 = 0.0f;
        if (extra) v24 = __ldcs(Sp + (long long)sj24 * NC);

        // coalesced streaming stores
#pragma unroll
        for (int t = 0; t < JBASE; t++)
            __stcs(o + (jbeg + t) * NC, v[t]);
        if (extra) __stcs(o + (jbeg + JBASE) * NC, v24);
    }
}

// ---------------------------------------------------------------------------
// Launch: d_in[0] = mu_in [8,28,28,32] f32, d_in[1] = Sigma_in [8,784,784,32] f32
// d_out = mu_out (50176 floats) followed by Sigma_out (9834496 floats).
// ---------------------------------------------------------------------------
extern "C" void kernel_launch(void* const* d_in, const int* in_sizes, int n_in,
                              void* d_out, int out_size) {
    const float* mu    = (const float*)d_in[0];
    const float* Sigma = (const float*)d_in[1];
    float* out   = (float*)d_out;
    float* outMu = out;
    float* outS  = out + NB * NOUT * NC;   // 50176

    // Cap L2->DRAM fetch granularity at 32B (proven 90.2us -> 61.5us win).
    // Device-persistent; establish on the non-captured correctness call,
    // skip during graph capture (no captured side effects).
    cudaStreamCaptureStatus st = cudaStreamCaptureStatusNone;
    cudaStreamIsCapturing((cudaStream_t)0, &st);
    if (st == cudaStreamCaptureStatusNone) {
        (void)cudaDeviceSetLimit(cudaLimitMaxL2FetchGranularity, 32);
    }

    pool_idx_kernel<<<(NB * NOUT * NC + 511) / 512, 512>>>(mu, outMu);

    // Programmatic dependent launch: B's prologue overlaps A + launch latency.
    cudaLaunchAttribute attrs[1];
    attrs[0].id = cudaLaunchAttributeProgrammaticStreamSerialization;
    attrs[0].val.programmaticStreamSerializationAllowed = 1;
    cudaLaunchConfig_t cfg = {};
    cfg.gridDim  = dim3(GRIDB, 1, 1);
    cfg.blockDim = dim3(256, 1, 1);
    cfg.dynamicSmemBytes = 0;
    cfg.stream = 0;
    cfg.attrs = attrs;
    cfg.numAttrs = 1;
    cudaLaunchKernelEx(&cfg, sigma_gather_kernel, Sigma, outS);
}

// round 17
// speedup vs baseline: 1.0345x; 1.0345x over previous
#include <cuda_runtime.h>
#include <cuda_bf16.h>

// Problem constants (fixed by the reference setup_inputs)
#define NB    8      // batch
#define HH    28     // input H = W
#define NC    32     // channels (== warp size == one 128B line of floats)
#define HO    14     // output H = W
#define NOUT  196    // HO*HO
#define NIN   784    // HH*HH

#define NTILE (NB * NOUT)   // 1568 (b,i) tiles
#define GRIDB (NTILE * 2)   // 3136 half-tile blocks, HW-scheduled

// Scratch: flat input spatial index of the per-(b,i,c) argmax,
// laid out [b][i][c] so a warp (lane=c) reads one coalesced line per i.
__device__ int g_sidx[NB * NOUT * NC];

// ---------------------------------------------------------------------------
// Kernel A: 2x2 max-pool argmax -> mu_out + gather index.
// One thread per (b, oy, ox, c); 50176 threads total (98 blocks x 512).
// ---------------------------------------------------------------------------
__global__ void pool_idx_kernel(const float* __restrict__ mu,
                                float* __restrict__ out_mu) {
    int t = blockIdx.x * blockDim.x + threadIdx.x;
    if (t < NB * NOUT * NC) {
        int c = t & (NC - 1);
        int p = t >> 5;            // b*196 + i
        int i = p % NOUT;
        int oy = i / HO, ox = i - oy * HO;
        int iy = 2 * oy, ix = 2 * ox;
        int b = p / NOUT;

        const float* base = mu + ((b * HH + iy) * HH + ix) * NC + c;
        float v00 = base[0];
        float v01 = base[NC];
        float v10 = base[HH * NC];
        float v11 = base[HH * NC + NC];

        // first-match argmax over row-major order (0,0),(0,1),(1,0),(1,1)
        float best = v00; int k = 0;
        if (v01 > best) { best = v01; k = 1; }
        if (v10 > best) { best = v10; k = 2; }
        if (v11 > best) { best = v11; k = 3; }
        int dy = k >> 1, dx = k & 1;

        out_mu[t] = best;
        g_sidx[t] = (iy + dy) * HH + (ix + dx);   // flat input spatial index
    }
    // PDL: allow the dependent gather kernel to begin its prologue early.
    cudaTriggerProgrammaticLaunchCompletion();
}

// ---------------------------------------------------------------------------
// Kernel B: Sigma double-gather — half-tile blocks, HW-scheduled balance.
// 3136 blocks x 128 threads (4 warps). Block owns (tile = blockIdx>>1,
// half = blockIdx&1); warp w handles chunk cw = half*4 + w (chunks 0-3:
// 25 j's, chunks 4-7: 24). No loops, no atomics, no barriers — the warp
// body is byte-identical to the proven R12 engine (48 regs, 24+1 deep
// back-to-back __ldcs gathers, coalesced __stcs stores). At 48 regs the
// reg file caps residency at 10 blocks/SM = 40 warps/SM — same in-flight
// gather product as R12, but the last-wave tail shrinks from a full-tile
// wave to ~12% of one wave, with HW work-stealing doing the balancing.
// ---------------------------------------------------------------------------
#define JBASE 24

__global__ void __launch_bounds__(128)
sigma_gather_kernel(const float* __restrict__ S, float* __restrict__ outS) {
    int c = threadIdx.x & 31;
    int w = threadIdx.x >> 5;            // 0..3
    unsigned blk = blockIdx.x;
    unsigned tile = blk >> 1;
    int cw = (int)((blk & 1u) << 2) + w; // chunk id 0..7

    bool extra = (cw < 4);
    int jbeg = extra ? (cw * 25) : (100 + (cw - 4) * 24);

    int b = (int)tile / NOUT;

    float* __restrict__ o =
        outS + ((long long)tile * NOUT) * NC + c;
    const int* __restrict__ sj_base = &g_sidx[b * NOUT * NC + c];

    // Wait for pool_idx_kernel's g_sidx writes (PDL dependency).
    cudaGridDependencySynchronize();

    int my_sidx = __ldg(&g_sidx[tile * NC + c]);
    const float* __restrict__ Sp =
        S + (long long)b * (NIN * (long long)NIN * NC)
          + (long long)my_sidx * (NIN * NC) + c;

    // preload column spatial indices (L2-resident scratch)
    int sj[JBASE];
#pragma unroll
    for (int t = 0; t < JBASE; t++)
        sj[t] = __ldg(sj_base + (jbeg + t) * NC);
    int sj24 = 0;
    if (extra) sj24 = __ldg(sj_base + (jbeg + JBASE) * NC);

    // issue all gathers back-to-back (evict-first: zero reuse)
    float v[JBASE];
#pragma unroll
    for (int t = 0; t < JBASE; t++)
        v[t] = __ldcs(Sp + (long long)sj[t] * NC);
    float v24 = 0.0f;
    if (extra) v24 = __ldcs(Sp + (long long)sj24 * NC);

    // coalesced streaming stores
#pragma unroll
    for (int t = 0; t < JBASE; t++)
        __stcs(o + (jbeg + t) * NC, v[t]);
    if (extra) __stcs(o + (jbeg + JBASE) * NC, v24);
}

// ---------------------------------------------------------------------------
// Launch: d_in[0] = mu_in [8,28,28,32] f32, d_in[1] = Sigma_in [8,784,784,32] f32
// d_out = mu_out (50176 floats) followed by Sigma_out (9834496 floats).
// ---------------------------------------------------------------------------
extern "C" void kernel_launch(void* const* d_in, const int* in_sizes, int n_in,
                              void* d_out, int out_size) {
    const float* mu    = (const float*)d_in[0];
    const float* Sigma = (const float*)d_in[1];
    float* out   = (float*)d_out;
    float* outMu = out;
    float* outS  = out + NB * NOUT * NC;   // 50176

    // Cap L2->DRAM fetch granularity at 32B (proven 90.2us -> 61.5us win).
    // Device-persistent; establish on the non-captured correctness call,
    // skip during graph capture (no captured side effects).
    cudaStreamCaptureStatus st = cudaStreamCaptureStatusNone;
    cudaStreamIsCapturing((cudaStream_t)0, &st);
    if (st == cudaStreamCaptureStatusNone) {
        (void)cudaDeviceSetLimit(cudaLimitMaxL2FetchGranularity, 32);
    }

    pool_idx_kernel<<<(NB * NOUT * NC + 511) / 512, 512>>>(mu, outMu);

    // Programmatic dependent launch: B's prologue overlaps A + launch latency.
    cudaLaunchAttribute attrs[1];
    attrs[0].id = cudaLaunchAttributeProgrammaticStreamSerialization;
    attrs[0].val.programmaticStreamSerializationAllowed = 1;
    cudaLaunchConfig_t cfg = {};
    cfg.gridDim  = dim3(GRIDB, 1, 1);
    cfg.blockDim = dim3(128, 1, 1);
    cfg.dynamicSmemBytes = 0;
    cfg.stream = 0;
    cfg.attrs = attrs;
    cfg.numAttrs = 1;
    cudaLaunchKernelEx(&cfg, sigma_gather_kernel, Sigma, outS);
}